// round 1
// baseline (speedup 1.0000x reference)
#include <cuda_runtime.h>
#include <cstddef>

#define BB 4
#define NN 8192
#define CC 64
#define SS 2048
#define KK 32
#define R2 0.04f

#define GROUPED_OFF (BB * SS * 3)                      /* 24576 */
#define FPS_OFF (GROUPED_OFF + BB * (CC + 3) * SS * KK) /* 24576 + 17563648 */

// scratch (static device globals: no allocation in kernel_launch)
__device__ int   g_ballidx[BB * SS * KK];   // 1 MB
__device__ float g_ft[(size_t)BB * NN * CC]; // 8 MB, features transposed to (B,N,C)

// ---------------------------------------------------------------------------
// features (B,C,N) -> (B,N,C)
// ---------------------------------------------------------------------------
__global__ void transpose_kernel(const float* __restrict__ f) {
    __shared__ float tile[32][33];
    const int b  = blockIdx.z;
    const int n0 = blockIdx.x * 32;
    const int c0 = blockIdx.y * 32;
    const float* fb = f + (size_t)b * CC * NN;
#pragma unroll
    for (int j = 0; j < 32; j += 8)
        tile[threadIdx.y + j][threadIdx.x] =
            fb[(size_t)(c0 + threadIdx.y + j) * NN + (n0 + threadIdx.x)];
    __syncthreads();
    float* fo = g_ft + (size_t)b * NN * CC;
#pragma unroll
    for (int j = 0; j < 32; j += 8)
        fo[(size_t)(n0 + threadIdx.y + j) * CC + (c0 + threadIdx.x)] =
            tile[threadIdx.x][threadIdx.y + j];
}

// ---------------------------------------------------------------------------
// FPS: one block per batch, 1024 threads x 8 points each, coords+min_d in regs
// writes new_xyz (out[0..]) and fps_idx (out[FPS_OFF..], as float)
// ---------------------------------------------------------------------------
__global__ void __launch_bounds__(1024, 1)
fps_kernel(const float* __restrict__ xyz, float* __restrict__ out) {
    const int b = blockIdx.x;
    const float* base = xyz + (size_t)b * NN * 3;
    float* newxyz = out + (size_t)b * SS * 3;
    float* fpsout = out + FPS_OFF + (size_t)b * SS;
    const int t = threadIdx.x;

    float px[8], py[8], pz[8], md[8];
#pragma unroll
    for (int k = 0; k < 8; k++) {
        const int p = t + k * 1024;
        px[k] = base[p * 3 + 0];
        py[k] = base[p * 3 + 1];
        pz[k] = base[p * 3 + 2];
        md[k] = 1e10f;
    }

    __shared__ float s_last[3];
    __shared__ float s_rv[32];
    __shared__ int   s_ri[32];

    if (t == 0) {
        s_last[0] = px[0]; s_last[1] = py[0]; s_last[2] = pz[0];
        fpsout[0] = 0.0f;
        newxyz[0] = px[0]; newxyz[1] = py[0]; newxyz[2] = pz[0];
    }
    __syncthreads();

    for (int i = 1; i < SS; i++) {
        const float cx = s_last[0], cy = s_last[1], cz = s_last[2];
        float bv = -1.0f;
        int   bi = 0;
#pragma unroll
        for (int k = 0; k < 8; k++) {
            const float dx = px[k] - cx;
            const float dy = py[k] - cy;
            const float dz = pz[k] - cz;
            const float d  = __fmaf_rn(dz, dz, __fmaf_rn(dy, dy, __fmul_rn(dx, dx)));
            const float m  = fminf(md[k], d);
            md[k] = m;
            if (m > bv) { bv = m; bi = t + k * 1024; }  // ascending idx in k => first-max kept
        }
        // warp argmax, lowest-index tie-break (matches jnp.argmax)
#pragma unroll
        for (int off = 16; off > 0; off >>= 1) {
            const float ov = __shfl_down_sync(0xffffffffu, bv, off);
            const int   oi = __shfl_down_sync(0xffffffffu, bi, off);
            if (ov > bv || (ov == bv && oi < bi)) { bv = ov; bi = oi; }
        }
        if ((t & 31) == 0) { s_rv[t >> 5] = bv; s_ri[t >> 5] = bi; }
        __syncthreads();
        if (t < 32) {
            bv = s_rv[t]; bi = s_ri[t];
#pragma unroll
            for (int off = 16; off > 0; off >>= 1) {
                const float ov = __shfl_down_sync(0xffffffffu, bv, off);
                const int   oi = __shfl_down_sync(0xffffffffu, bi, off);
                if (ov > bv || (ov == bv && oi < bi)) { bv = ov; bi = oi; }
            }
            if (t == 0) {
                const float nx = base[(size_t)bi * 3 + 0];
                const float ny = base[(size_t)bi * 3 + 1];
                const float nz = base[(size_t)bi * 3 + 2];
                s_last[0] = nx; s_last[1] = ny; s_last[2] = nz;
                fpsout[i] = (float)bi;
                newxyz[(size_t)i * 3 + 0] = nx;
                newxyz[(size_t)i * 3 + 1] = ny;
                newxyz[(size_t)i * 3 + 2] = nz;
            }
        }
        __syncthreads();
    }
}

// ---------------------------------------------------------------------------
// ball query: one warp per center; first K hits in index order via ballot/popc,
// pad with first hit (0 if none). Early exit when K found.
// ---------------------------------------------------------------------------
__global__ void ballquery_kernel(const float* __restrict__ xyz,
                                 const float* __restrict__ out) {
    __shared__ int sidx[8][KK];
    const int w    = threadIdx.x >> 5;
    const int lane = threadIdx.x & 31;
    const int cid  = blockIdx.x * 8 + w;   // grid = B*S/8 -> same batch per block
    const int b = cid / SS;
    const float* c = out + (size_t)cid * 3;      // new_xyz lives at start of out
    const float cx = c[0], cy = c[1], cz = c[2];
    const float* base = xyz + (size_t)b * NN * 3;

    sidx[w][lane] = 0;
    int cnt = 0;
    for (int p0 = 0; p0 < NN && cnt < KK; p0 += 32) {
        const int p = p0 + lane;
        const float dx = base[p * 3 + 0] - cx;
        const float dy = base[p * 3 + 1] - cy;
        const float dz = base[p * 3 + 2] - cz;
        const float d2 = __fmaf_rn(dz, dz, __fmaf_rn(dy, dy, __fmul_rn(dx, dx)));
        const bool hit = d2 < R2;
        const unsigned m = __ballot_sync(0xffffffffu, hit);
        if (m) {
            if (cnt == 0) {
                const int first = p0 + (__ffs(m) - 1);
                sidx[w][lane] = first;      // pad all K slots with first hit
            }
            __syncwarp();
            if (hit) {
                const int slot = cnt + __popc(m & ((1u << lane) - 1u));
                if (slot < KK) sidx[w][slot] = p;
            }
            cnt += __popc(m);
        }
    }
    __syncwarp();
    g_ballidx[(size_t)cid * KK + lane] = sidx[w][lane];
}

// ---------------------------------------------------------------------------
// grouping: one block per center. Coalesced 256B feature-row reads via smem,
// coalesced K-contiguous channel-major writes.
// out grouped layout: (B, 3+C, S, K), channels 0..2 = recentered xyz
// ---------------------------------------------------------------------------
__global__ void group_kernel(const float* __restrict__ xyz,
                             float* __restrict__ out) {
    const int cid = blockIdx.x;
    const int b = cid / SS, s = cid % SS;
    __shared__ int   sidx[KK];
    __shared__ float rel[3][KK];
    __shared__ float sf[KK][CC + 1];
    const int tid = threadIdx.x;

    if (tid < KK) {
        const int id = g_ballidx[(size_t)cid * KK + tid];
        sidx[tid] = id;
        const float* c = out + (size_t)cid * 3;
        const float* p = xyz + ((size_t)b * NN + id) * 3;
        rel[0][tid] = p[0] - c[0];
        rel[1][tid] = p[1] - c[1];
        rel[2][tid] = p[2] - c[2];
    }
    __syncthreads();

    const int cch = tid & 63;
    const int k0  = tid >> 6;   // 0..3
    const float* ftb = g_ft + (size_t)b * NN * CC;
#pragma unroll
    for (int j = 0; j < 8; j++) {
        const int k = k0 * 8 + j;
        sf[k][cch] = ftb[(size_t)sidx[k] * CC + cch];
    }
    __syncthreads();

    float* og = out + GROUPED_OFF + (size_t)b * (CC + 3) * SS * KK + (size_t)s * KK;
    if (tid < 96) {
        const int ch = tid >> 5, k = tid & 31;
        og[(size_t)ch * (SS * KK) + k] = rel[ch][k];
    }
    const int k  = tid & 31;
    const int cg = tid >> 5;    // 0..7
#pragma unroll
    for (int j = 0; j < 8; j++) {
        const int c2 = cg * 8 + j;
        og[(size_t)(3 + c2) * (SS * KK) + k] = sf[k][c2];
    }
}

// ---------------------------------------------------------------------------
extern "C" void kernel_launch(void* const* d_in, const int* in_sizes, int n_in,
                              void* d_out, int out_size) {
    const float* xyz  = (const float*)d_in[0];
    const float* feat = (const float*)d_in[1];
    float* out = (float*)d_out;

    transpose_kernel<<<dim3(NN / 32, CC / 32, BB), dim3(32, 8)>>>(feat);
    fps_kernel<<<BB, 1024>>>(xyz, out);
    ballquery_kernel<<<(BB * SS) / 8, 256>>>(xyz, out);
    group_kernel<<<BB * SS, 256>>>(xyz, out);
}

// round 2
// speedup vs baseline: 1.6038x; 1.6038x over previous
#include <cuda_runtime.h>
#include <cstddef>

#define BB 4
#define NN 8192
#define CC 64
#define SS 2048
#define KK 32
#define R2 0.04f

#define GROUPED_OFF (BB * SS * 3)                       /* 24576 */
#define FPS_OFF (GROUPED_OFF + BB * (CC + 3) * SS * KK) /* 24576 + 17563648 */

// scratch (static device globals: no allocation in kernel_launch)
__device__ int   g_ballidx[BB * SS * KK];    // 1 MB
__device__ float g_ft[(size_t)BB * NN * CC]; // 8 MB, features transposed to (B,N,C)

// ---------------------------------------------------------------------------
// packed f32x2 helpers (Blackwell FFMA2 path — only reachable via PTX f32x2)
// ---------------------------------------------------------------------------
typedef unsigned long long u64;

__device__ __forceinline__ u64 pk2(float lo, float hi) {
    u64 r; asm("mov.b64 %0, {%1, %2};" : "=l"(r) : "f"(lo), "f"(hi)); return r;
}
__device__ __forceinline__ void upk2(u64 v, float& lo, float& hi) {
    asm("mov.b64 {%0, %1}, %2;" : "=f"(lo), "=f"(hi) : "l"(v));
}
__device__ __forceinline__ u64 add2(u64 a, u64 b) {
    u64 r; asm("add.rn.f32x2 %0, %1, %2;" : "=l"(r) : "l"(a), "l"(b)); return r;
}
__device__ __forceinline__ u64 mul2(u64 a, u64 b) {
    u64 r; asm("mul.rn.f32x2 %0, %1, %2;" : "=l"(r) : "l"(a), "l"(b)); return r;
}
__device__ __forceinline__ u64 fma2(u64 a, u64 b, u64 c) {
    u64 r; asm("fma.rn.f32x2 %0, %1, %2, %3;" : "=l"(r) : "l"(a), "l"(b), "l"(c)); return r;
}

// ---------------------------------------------------------------------------
// features (B,C,N) -> (B,N,C)
// ---------------------------------------------------------------------------
__global__ void transpose_kernel(const float* __restrict__ f) {
    __shared__ float tile[32][33];
    const int b  = blockIdx.z;
    const int n0 = blockIdx.x * 32;
    const int c0 = blockIdx.y * 32;
    const float* fb = f + (size_t)b * CC * NN;
#pragma unroll
    for (int j = 0; j < 32; j += 8)
        tile[threadIdx.y + j][threadIdx.x] =
            fb[(size_t)(c0 + threadIdx.y + j) * NN + (n0 + threadIdx.x)];
    __syncthreads();
    float* fo = g_ft + (size_t)b * NN * CC;
#pragma unroll
    for (int j = 0; j < 32; j += 8)
        fo[(size_t)(n0 + threadIdx.y + j) * CC + (c0 + threadIdx.x)] =
            tile[threadIdx.x][threadIdx.y + j];
}

// ---------------------------------------------------------------------------
// FPS: one block per batch, 1024 threads x 8 points each.
// Packed f32x2 distance math; FMNMX tracking; REDUX reductions.
// writes new_xyz (out[0..]) and fps_idx (out[FPS_OFF..], as float)
// ---------------------------------------------------------------------------
__global__ void __launch_bounds__(1024, 1)
fps_kernel(const float* __restrict__ xyz, float* __restrict__ out) {
    const int b = blockIdx.x;
    const float* base = xyz + (size_t)b * NN * 3;
    float* newxyz = out + (size_t)b * SS * 3;
    float* fpsout = out + FPS_OFF + (size_t)b * SS;
    const int t = threadIdx.x;
    const int lane = t & 31;
    const int warp = t >> 5;

    // pair j holds points (t + 2j*1024, t + (2j+1)*1024): lo = even k, hi = odd k
    u64 pxp[4], pyp[4], pzp[4];
    float md[8];
#pragma unroll
    for (int j = 0; j < 4; j++) {
        const int p0 = t + (2 * j) * 1024;
        const int p1 = t + (2 * j + 1) * 1024;
        pxp[j] = pk2(base[p0 * 3 + 0], base[p1 * 3 + 0]);
        pyp[j] = pk2(base[p0 * 3 + 1], base[p1 * 3 + 1]);
        pzp[j] = pk2(base[p0 * 3 + 2], base[p1 * 3 + 2]);
        md[2 * j] = 1e10f; md[2 * j + 1] = 1e10f;
    }

    __shared__ float s_last[3];
    __shared__ unsigned s_rv[32];
    __shared__ int      s_ri[32];

    if (t == 0) {
        float lx, hx; upk2(pxp[0], lx, hx);
        float ly, hy; upk2(pyp[0], ly, hy);
        float lz, hz; upk2(pzp[0], lz, hz);
        s_last[0] = lx; s_last[1] = ly; s_last[2] = lz;
        fpsout[0] = 0.0f;
        newxyz[0] = lx; newxyz[1] = ly; newxyz[2] = lz;
    }
    __syncthreads();

    for (int i = 1; i < SS; i++) {
        const float cx = s_last[0], cy = s_last[1], cz = s_last[2];
        const u64 ncx = pk2(-cx, -cx);
        const u64 ncy = pk2(-cy, -cy);
        const u64 ncz = pk2(-cz, -cz);

        float bv = -1.0f;
#pragma unroll
        for (int j = 0; j < 4; j++) {
            const u64 dx = add2(pxp[j], ncx);
            const u64 dy = add2(pyp[j], ncy);
            const u64 dz = add2(pzp[j], ncz);
            const u64 d  = fma2(dz, dz, fma2(dy, dy, mul2(dx, dx)));
            float dl, dh; upk2(d, dl, dh);
            md[2 * j]     = fminf(md[2 * j], dl);
            md[2 * j + 1] = fminf(md[2 * j + 1], dh);
            bv = fmaxf(bv, md[2 * j]);
            bv = fmaxf(bv, md[2 * j + 1]);
        }
        // first (lowest-k => lowest global idx) occurrence of the max
        int bi = 0;
#pragma unroll
        for (int k = 7; k >= 0; k--)
            if (md[k] == bv) bi = t + k * 1024;

        // warp reduce: md >= 0 so float bits are order-isomorphic to u32
        const unsigned ubv = __float_as_uint(bv);
        const unsigned wmax = __reduce_max_sync(0xffffffffu, ubv);
        const unsigned cand = (ubv == wmax) ? (unsigned)bi : 0xffffffffu;
        const unsigned wbi  = __reduce_min_sync(0xffffffffu, cand);
        if (lane == 0) { s_rv[warp] = wmax; s_ri[warp] = (int)wbi; }
        __syncthreads();
        if (warp == 0) {
            const unsigned v = s_rv[lane];
            const int      x = s_ri[lane];
            const unsigned bmax = __reduce_max_sync(0xffffffffu, v);
            const unsigned c2   = (v == bmax) ? (unsigned)x : 0xffffffffu;
            const unsigned bbi  = __reduce_min_sync(0xffffffffu, c2);
            if (lane == 0) {
                const int gi = (int)bbi;
                const float nx = base[(size_t)gi * 3 + 0];
                const float ny = base[(size_t)gi * 3 + 1];
                const float nz = base[(size_t)gi * 3 + 2];
                s_last[0] = nx; s_last[1] = ny; s_last[2] = nz;
                fpsout[i] = (float)gi;
                newxyz[(size_t)i * 3 + 0] = nx;
                newxyz[(size_t)i * 3 + 1] = ny;
                newxyz[(size_t)i * 3 + 2] = nz;
            }
        }
        __syncthreads();
    }
}

// ---------------------------------------------------------------------------
// ball query: one warp per center; first K hits in index order via ballot/popc,
// pad with first hit (0 if none). Early exit when K found.
// ---------------------------------------------------------------------------
__global__ void ballquery_kernel(const float* __restrict__ xyz,
                                 const float* __restrict__ out) {
    __shared__ int sidx[8][KK];
    const int w    = threadIdx.x >> 5;
    const int lane = threadIdx.x & 31;
    const int cid  = blockIdx.x * 8 + w;
    const int b = cid / SS;
    const float* c = out + (size_t)cid * 3;      // new_xyz lives at start of out
    const float cx = c[0], cy = c[1], cz = c[2];
    const float* base = xyz + (size_t)b * NN * 3;

    sidx[w][lane] = 0;
    int cnt = 0;
    for (int p0 = 0; p0 < NN && cnt < KK; p0 += 32) {
        const int p = p0 + lane;
        const float dx = base[p * 3 + 0] - cx;
        const float dy = base[p * 3 + 1] - cy;
        const float dz = base[p * 3 + 2] - cz;
        const float d2 = __fmaf_rn(dz, dz, __fmaf_rn(dy, dy, __fmul_rn(dx, dx)));
        const bool hit = d2 < R2;
        const unsigned m = __ballot_sync(0xffffffffu, hit);
        if (m) {
            if (cnt == 0) {
                const int first = p0 + (__ffs(m) - 1);
                sidx[w][lane] = first;      // pad all K slots with first hit
            }
            __syncwarp();
            if (hit) {
                const int slot = cnt + __popc(m & ((1u << lane) - 1u));
                if (slot < KK) sidx[w][slot] = p;
            }
            cnt += __popc(m);
        }
    }
    __syncwarp();
    g_ballidx[(size_t)cid * KK + lane] = sidx[w][lane];
}

// ---------------------------------------------------------------------------
// grouping: one block per center. Coalesced 256B feature-row reads via smem,
// coalesced K-contiguous channel-major writes.
// out grouped layout: (B, 3+C, S, K), channels 0..2 = recentered xyz
// ---------------------------------------------------------------------------
__global__ void group_kernel(const float* __restrict__ xyz,
                             float* __restrict__ out) {
    const int cid = blockIdx.x;
    const int b = cid / SS, s = cid % SS;
    __shared__ int   sidx[KK];
    __shared__ float rel[3][KK];
    __shared__ float sf[KK][CC + 1];
    const int tid = threadIdx.x;

    if (tid < KK) {
        const int id = g_ballidx[(size_t)cid * KK + tid];
        sidx[tid] = id;
        const float* c = out + (size_t)cid * 3;
        const float* p = xyz + ((size_t)b * NN + id) * 3;
        rel[0][tid] = p[0] - c[0];
        rel[1][tid] = p[1] - c[1];
        rel[2][tid] = p[2] - c[2];
    }
    __syncthreads();

    const int cch = tid & 63;
    const int k0  = tid >> 6;   // 0..3
    const float* ftb = g_ft + (size_t)b * NN * CC;
#pragma unroll
    for (int j = 0; j < 8; j++) {
        const int k = k0 * 8 + j;
        sf[k][cch] = ftb[(size_t)sidx[k] * CC + cch];
    }
    __syncthreads();

    float* og = out + GROUPED_OFF + (size_t)b * (CC + 3) * SS * KK + (size_t)s * KK;
    if (tid < 96) {
        const int ch = tid >> 5, k = tid & 31;
        og[(size_t)ch * (SS * KK) + k] = rel[ch][k];
    }
    const int k  = tid & 31;
    const int cg = tid >> 5;    // 0..7
#pragma unroll
    for (int j = 0; j < 8; j++) {
        const int c2 = cg * 8 + j;
        og[(size_t)(3 + c2) * (SS * KK) + k] = sf[k][c2];
    }
}

// ---------------------------------------------------------------------------
extern "C" void kernel_launch(void* const* d_in, const int* in_sizes, int n_in,
                              void* d_out, int out_size) {
    const float* xyz  = (const float*)d_in[0];
    const float* feat = (const float*)d_in[1];
    float* out = (float*)d_out;

    transpose_kernel<<<dim3(NN / 32, CC / 32, BB), dim3(32, 8)>>>(feat);
    fps_kernel<<<BB, 1024>>>(xyz, out);
    ballquery_kernel<<<(BB * SS) / 8, 256>>>(xyz, out);
    group_kernel<<<BB * SS, 256>>>(xyz, out);
}

// round 3
// speedup vs baseline: 1.8547x; 1.1564x over previous
#include <cuda_runtime.h>
#include <cstddef>

#define BB 4
#define NN 8192
#define CC 64
#define SS 2048
#define KK 32
#define R2 0.04f

#define GROUPED_OFF (BB * SS * 3)                       /* 24576 */
#define FPS_OFF (GROUPED_OFF + BB * (CC + 3) * SS * KK) /* 24576 + 17563648 */

// scratch (static device globals: no allocation in kernel_launch)
__device__ int   g_ballidx[BB * SS * KK];    // 1 MB
__device__ float g_ft[(size_t)BB * NN * CC]; // 8 MB, features transposed to (B,N,C)

// ---------------------------------------------------------------------------
// packed f32x2 helpers (Blackwell FFMA2 path — only reachable via PTX f32x2)
// ---------------------------------------------------------------------------
typedef unsigned long long u64;

__device__ __forceinline__ u64 pk2(float lo, float hi) {
    u64 r; asm("mov.b64 %0, {%1, %2};" : "=l"(r) : "f"(lo), "f"(hi)); return r;
}
__device__ __forceinline__ void upk2(u64 v, float& lo, float& hi) {
    asm("mov.b64 {%0, %1}, %2;" : "=f"(lo), "=f"(hi) : "l"(v));
}
__device__ __forceinline__ u64 add2(u64 a, u64 b) {
    u64 r; asm("add.rn.f32x2 %0, %1, %2;" : "=l"(r) : "l"(a), "l"(b)); return r;
}
__device__ __forceinline__ u64 mul2(u64 a, u64 b) {
    u64 r; asm("mul.rn.f32x2 %0, %1, %2;" : "=l"(r) : "l"(a), "l"(b)); return r;
}
__device__ __forceinline__ u64 fma2(u64 a, u64 b, u64 c) {
    u64 r; asm("fma.rn.f32x2 %0, %1, %2, %3;" : "=l"(r) : "l"(a), "l"(b), "l"(c)); return r;
}

// ---------------------------------------------------------------------------
// features (B,C,N) -> (B,N,C)
// ---------------------------------------------------------------------------
__global__ void transpose_kernel(const float* __restrict__ f) {
    __shared__ float tile[32][33];
    const int b  = blockIdx.z;
    const int n0 = blockIdx.x * 32;
    const int c0 = blockIdx.y * 32;
    const float* fb = f + (size_t)b * CC * NN;
#pragma unroll
    for (int j = 0; j < 32; j += 8)
        tile[threadIdx.y + j][threadIdx.x] =
            fb[(size_t)(c0 + threadIdx.y + j) * NN + (n0 + threadIdx.x)];
    __syncthreads();
    float* fo = g_ft + (size_t)b * NN * CC;
#pragma unroll
    for (int j = 0; j < 32; j += 8)
        fo[(size_t)(n0 + threadIdx.y + j) * CC + (c0 + threadIdx.x)] =
            tile[threadIdx.x][threadIdx.y + j];
}

// ---------------------------------------------------------------------------
// FPS: one block of 256 threads per batch, 32 points per thread.
// Packed f32x2 distance math, pre-negated coords, single-barrier iteration
// with double-buffered leader slots and redundant per-warp final reduction.
// writes new_xyz (out[0..]) and fps_idx (out[FPS_OFF..], as float)
// ---------------------------------------------------------------------------
__global__ void __launch_bounds__(256, 1)
fps_kernel(const float* __restrict__ xyz, float* __restrict__ out) {
    const int b = blockIdx.x;
    const float* base = xyz + (size_t)b * NN * 3;
    float* newxyz = out + (size_t)b * SS * 3;
    float* fpsout = out + FPS_OFF + (size_t)b * SS;
    const int t = threadIdx.x;
    const int lane = t & 31;

    // pair j holds points (t + 2j*256, t + (2j+1)*256), stored NEGATED
    u64 npx[16], npy[16], npz[16];
    float md[32];
#pragma unroll
    for (int j = 0; j < 16; j++) {
        const int p0 = t + (2 * j) * 256;
        const int p1 = t + (2 * j + 1) * 256;
        npx[j] = pk2(-base[p0 * 3 + 0], -base[p1 * 3 + 0]);
        npy[j] = pk2(-base[p0 * 3 + 1], -base[p1 * 3 + 1]);
        npz[j] = pk2(-base[p0 * 3 + 2], -base[p1 * 3 + 2]);
        md[2 * j] = 1e10f; md[2 * j + 1] = 1e10f;
    }

    __shared__ unsigned s_val[2][32];
    __shared__ unsigned s_idx[2][32];
    if (t < 32) {
        s_val[0][t] = 0u; s_val[1][t] = 0u;
        s_idx[0][t] = 0xffffffffu; s_idx[1][t] = 0xffffffffu;
    }
    // padding writes are ordered before first read by the bar inside iter 1

    float cx = base[0], cy = base[1], cz = base[2];
    if (t == 0) {
        fpsout[0] = 0.0f;
        newxyz[0] = cx; newxyz[1] = cy; newxyz[2] = cz;
    }

    for (int i = 1; i < SS; i++) {
        const int buf = i & 1;
        const u64 cx2 = pk2(cx, cx);
        const u64 cy2 = pk2(cy, cy);
        const u64 cz2 = pk2(cz, cz);

        float m2[16];
#pragma unroll
        for (int j = 0; j < 16; j++) {
            const u64 dx = add2(cx2, npx[j]);          // cx - px
            const u64 dy = add2(cy2, npy[j]);
            const u64 dz = add2(cz2, npz[j]);
            const u64 d  = fma2(dz, dz, fma2(dy, dy, mul2(dx, dx)));
            float dl, dh; upk2(d, dl, dh);
            md[2 * j]     = fminf(md[2 * j], dl);
            md[2 * j + 1] = fminf(md[2 * j + 1], dh);
            m2[j] = fmaxf(md[2 * j], md[2 * j + 1]);
        }
        float m4[8];
#pragma unroll
        for (int j = 0; j < 8; j++) m4[j] = fmaxf(m2[2 * j], m2[2 * j + 1]);
        float m8[4];
#pragma unroll
        for (int j = 0; j < 4; j++) m8[j] = fmaxf(m4[2 * j], m4[2 * j + 1]);
        const float bv = fmaxf(fmaxf(m8[0], m8[1]), fmaxf(m8[2], m8[3]));

        // first (lowest-k => lowest global idx) occurrence of the max
        int bi = 0;
#pragma unroll
        for (int k = 31; k >= 0; k--)
            if (md[k] == bv) bi = t + k * 256;

        // warp reduce: md >= 0 so float bits are order-isomorphic to u32
        const unsigned ubv  = __float_as_uint(bv);
        const unsigned wmax = __reduce_max_sync(0xffffffffu, ubv);
        const unsigned cand = (ubv == wmax) ? (unsigned)bi : 0xffffffffu;
        const unsigned wbi  = __reduce_min_sync(0xffffffffu, cand);
        if (lane == 0) { s_val[buf][t >> 5] = wmax; s_idx[buf][t >> 5] = wbi; }
        __syncthreads();

        // every warp redundantly reduces the 8 leader slots (pads lose: val 0)
        const unsigned v = s_val[buf][lane];
        const unsigned x = s_idx[buf][lane];
        const unsigned bmax = __reduce_max_sync(0xffffffffu, v);
        const unsigned c2   = (v == bmax) ? x : 0xffffffffu;
        const int gi = (int)__reduce_min_sync(0xffffffffu, c2);

        cx = base[(size_t)gi * 3 + 0];   // same addr per warp -> L1 broadcast
        cy = base[(size_t)gi * 3 + 1];
        cz = base[(size_t)gi * 3 + 2];
        if (t == 0) {
            fpsout[i] = (float)gi;
            newxyz[(size_t)i * 3 + 0] = cx;
            newxyz[(size_t)i * 3 + 1] = cy;
            newxyz[(size_t)i * 3 + 2] = cz;
        }
    }
}

// ---------------------------------------------------------------------------
// ball query: one warp per center; first K hits in index order via ballot/popc,
// pad with first hit (0 if none). Early exit when K found.
// ---------------------------------------------------------------------------
__global__ void ballquery_kernel(const float* __restrict__ xyz,
                                 const float* __restrict__ out) {
    __shared__ int sidx[8][KK];
    const int w    = threadIdx.x >> 5;
    const int lane = threadIdx.x & 31;
    const int cid  = blockIdx.x * 8 + w;
    const int b = cid / SS;
    const float* c = out + (size_t)cid * 3;      // new_xyz lives at start of out
    const float cx = c[0], cy = c[1], cz = c[2];
    const float* base = xyz + (size_t)b * NN * 3;

    sidx[w][lane] = 0;
    int cnt = 0;
    for (int p0 = 0; p0 < NN && cnt < KK; p0 += 32) {
        const int p = p0 + lane;
        const float dx = base[p * 3 + 0] - cx;
        const float dy = base[p * 3 + 1] - cy;
        const float dz = base[p * 3 + 2] - cz;
        const float d2 = __fmaf_rn(dz, dz, __fmaf_rn(dy, dy, __fmul_rn(dx, dx)));
        const bool hit = d2 < R2;
        const unsigned m = __ballot_sync(0xffffffffu, hit);
        if (m) {
            if (cnt == 0) {
                const int first = p0 + (__ffs(m) - 1);
                sidx[w][lane] = first;      // pad all K slots with first hit
            }
            __syncwarp();
            if (hit) {
                const int slot = cnt + __popc(m & ((1u << lane) - 1u));
                if (slot < KK) sidx[w][slot] = p;
            }
            cnt += __popc(m);
        }
    }
    __syncwarp();
    g_ballidx[(size_t)cid * KK + lane] = sidx[w][lane];
}

// ---------------------------------------------------------------------------
// grouping: one block per center. Coalesced 256B feature-row reads via smem,
// coalesced K-contiguous channel-major writes.
// out grouped layout: (B, 3+C, S, K), channels 0..2 = recentered xyz
// ---------------------------------------------------------------------------
__global__ void group_kernel(const float* __restrict__ xyz,
                             float* __restrict__ out) {
    const int cid = blockIdx.x;
    const int b = cid / SS, s = cid % SS;
    __shared__ int   sidx[KK];
    __shared__ float rel[3][KK];
    __shared__ float sf[KK][CC + 1];
    const int tid = threadIdx.x;

    if (tid < KK) {
        const int id = g_ballidx[(size_t)cid * KK + tid];
        sidx[tid] = id;
        const float* c = out + (size_t)cid * 3;
        const float* p = xyz + ((size_t)b * NN + id) * 3;
        rel[0][tid] = p[0] - c[0];
        rel[1][tid] = p[1] - c[1];
        rel[2][tid] = p[2] - c[2];
    }
    __syncthreads();

    const int cch = tid & 63;
    const int k0  = tid >> 6;   // 0..3
    const float* ftb = g_ft + (size_t)b * NN * CC;
#pragma unroll
    for (int j = 0; j < 8; j++) {
        const int k = k0 * 8 + j;
        sf[k][cch] = ftb[(size_t)sidx[k] * CC + cch];
    }
    __syncthreads();

    float* og = out + GROUPED_OFF + (size_t)b * (CC + 3) * SS * KK + (size_t)s * KK;
    if (tid < 96) {
        const int ch = tid >> 5, k = tid & 31;
        og[(size_t)ch * (SS * KK) + k] = rel[ch][k];
    }
    const int k  = tid & 31;
    const int cg = tid >> 5;    // 0..7
#pragma unroll
    for (int j = 0; j < 8; j++) {
        const int c2 = cg * 8 + j;
        og[(size_t)(3 + c2) * (SS * KK) + k] = sf[k][c2];
    }
}

// ---------------------------------------------------------------------------
extern "C" void kernel_launch(void* const* d_in, const int* in_sizes, int n_in,
                              void* d_out, int out_size) {
    const float* xyz  = (const float*)d_in[0];
    const float* feat = (const float*)d_in[1];
    float* out = (float*)d_out;

    transpose_kernel<<<dim3(NN / 32, CC / 32, BB), dim3(32, 8)>>>(feat);
    fps_kernel<<<BB, 256>>>(xyz, out);
    ballquery_kernel<<<(BB * SS) / 8, 256>>>(xyz, out);
    group_kernel<<<BB * SS, 256>>>(xyz, out);
}